// round 17
// baseline (speedup 1.0000x reference)
#include <cuda_runtime.h>
#include <cuda_bf16.h>
#include <cmath>

#define T_  200
#define B_  256
#define M_  (T_ * B_)      // 51200 rows

__device__ float g_xproj[M_ * 200];  // [T,B,4H] flat row r = t*256+b
__device__ float g_hs[M_ * 50];      // [T,B,H]

// ---------------- helpers ----------------
__device__ __forceinline__ unsigned long long fma2(unsigned long long a,
                                                   unsigned long long b,
                                                   unsigned long long c) {
    unsigned long long d;
    asm("fma.rn.f32x2 %0, %1, %2, %3;" : "=l"(d) : "l"(a), "l"(b), "l"(c));
    return d;
}
__device__ __forceinline__ unsigned long long add2(unsigned long long a,
                                                   unsigned long long b) {
    unsigned long long d;
    asm("add.rn.f32x2 %0, %1, %2;" : "=l"(d) : "l"(a), "l"(b));
    return d;
}
__device__ __forceinline__ float2 u2f(unsigned long long v) {
    float2 r;
    asm("mov.b64 {%0, %1}, %2;" : "=f"(r.x), "=f"(r.y) : "l"(v));
    return r;
}
__device__ __forceinline__ unsigned smem_u32(const void* p) {
    return (unsigned)__cvta_generic_to_shared(p);
}
__device__ __forceinline__ void cp16(unsigned dst, const void* src) {
    asm volatile("cp.async.cg.shared.global [%0], [%1], 16;" :: "r"(dst), "l"(src));
}
__device__ __forceinline__ float frcp(float x) {
    float r; asm("rcp.approx.f32 %0, %1;" : "=f"(r) : "f"(x)); return r;
}
__device__ __forceinline__ float sigm(float x) {
    return frcp(1.f + __expf(-x));
}

__device__ __forceinline__ void mma_bf16(float* c, const unsigned* a,
                                         unsigned b0, unsigned b1) {
    asm volatile(
        "mma.sync.aligned.m16n8k16.row.col.f32.bf16.bf16.f32 "
        "{%0,%1,%2,%3}, {%4,%5,%6,%7}, {%8,%9}, {%0,%1,%2,%3};"
        : "+f"(c[0]), "+f"(c[1]), "+f"(c[2]), "+f"(c[3])
        : "r"(a[0]), "r"(a[1]), "r"(a[2]), "r"(a[3]), "r"(b0), "r"(b1));
}
__device__ __forceinline__ void ldsm_x4(unsigned* r, unsigned addr) {
    asm volatile(
        "ldmatrix.sync.aligned.m8n8.x4.shared.b16 {%0,%1,%2,%3}, [%4];"
        : "=r"(r[0]), "=r"(r[1]), "=r"(r[2]), "=r"(r[3]) : "r"(addr));
}
__device__ __forceinline__ void bf16_split(float x, __nv_bfloat16& h,
                                           __nv_bfloat16& l) {
    h = __float2bfloat16_rn(x);
    l = __float2bfloat16_rn(x - __bfloat162float(h));
}
__device__ __forceinline__ unsigned pack_bf2(__nv_bfloat16 lo16, __nv_bfloat16 hi16) {
    __nv_bfloat16 x2[2] = {lo16, hi16};
    return *reinterpret_cast<unsigned*>(x2);
}

// ---------------------------------------------------------------------------
// K1 (tensor, v2 + token prefetch): unchanged from R14 (~45us)
// ---------------------------------------------------------------------------
#define K1_SMEM_WORDS 34504   // 138,016 bytes

__global__ __launch_bounds__(512, 1) void k1_mma(
    const int*   __restrict__ tokens,
    const float* __restrict__ emb,
    const float* __restrict__ Wih,
    const float* __restrict__ bih,
    const float* __restrict__ bhh)
{
    extern __shared__ __align__(16) float sm[];
    unsigned* BHI  = reinterpret_cast<unsigned*>(sm);
    unsigned* BLO  = reinterpret_cast<unsigned*>(sm + 12800);
    unsigned* AHI  = reinterpret_cast<unsigned*>(sm + 25600);
    unsigned* ALO  = reinterpret_cast<unsigned*>(sm + 29952);
    float*    bsum = sm + 34304;

    const int tid  = threadIdx.x;
    const int lane = tid & 31;
    const int wid  = tid >> 5;
    const int wm   = wid >> 3;
    const int ng   = wid & 7;
    const int ntb  = (ng == 0) ? 0 : (4 + 3 * (ng - 1));
    const int ncnt = (ng == 0) ? 4 : 3;

    const int r_ln = lane >> 2;
    const int c_ln = lane & 3;

    const int lrow  = (lane & 7) + ((lane >> 3) & 1) * 8;
    const int khalf = lane >> 4;
    int aoff[2];
#pragma unroll
    for (int f = 0; f < 2; f++)
        aoff[f] = (wm * 32 + f * 16 + lrow) * 68 + khalf * 4;
    const unsigned ahi_b = smem_u32(AHI);
    const unsigned alo_b = smem_u32(ALO);

    for (int i = tid; i < 12800; i += 512) {
        const int nn = i >> 6;
        const int kp = i & 63;
        const int s  = kp >> 3;
        const int hh = (kp >> 2) & 1;
        const int cc = kp & 3;
        const int nt = nn >> 3;
        const int gg = nn & 7;
        const int dst = (((s * 25 + nt) * 32) + gg * 4 + cc) * 2 + hh;
        const float2 v = *reinterpret_cast<const float2*>(Wih + nn * 128 + 2 * kp);
        __nv_bfloat16 h0, l0, h1, l1;
        bf16_split(v.x, h0, l0);
        bf16_split(v.y, h1, l1);
        BHI[dst] = pack_bf2(h0, h1);
        BLO[dst] = pack_bf2(l0, l1);
    }
    if (tid < 200) bsum[tid] = bih[tid] + bhh[tid];

    const int grow = tid >> 3;
    const int gsub = tid & 7;

    int tok_next = tokens[blockIdx.x * 64 + grow];

    for (int tile = blockIdx.x; tile < 800; tile += 148) {
        const int row0 = tile * 64;
        const int tok  = tok_next;

        {
            const float4* src = reinterpret_cast<const float4*>(
                emb + (size_t)tok * 128 + gsub * 16);
            const float4 v0 = src[0], v1 = src[1], v2 = src[2], v3 = src[3];
            if (tile + 148 < 800) tok_next = tokens[(tile + 148) * 64 + grow];
            const float xsrc[16] = {v0.x, v0.y, v0.z, v0.w, v1.x, v1.y, v1.z, v1.w,
                                    v2.x, v2.y, v2.z, v2.w, v3.x, v3.y, v3.z, v3.w};
            unsigned hw[8], lw[8];
#pragma unroll
            for (int p = 0; p < 8; p++) {
                __nv_bfloat16 h0, l0, h1, l1;
                bf16_split(xsrc[2 * p],     h0, l0);
                bf16_split(xsrc[2 * p + 1], h1, l1);
                hw[p] = pack_bf2(h0, h1);
                lw[p] = pack_bf2(l0, l1);
            }
            const int wbase = grow * 68 + gsub * 8;
            *reinterpret_cast<uint4*>(&AHI[wbase]) =
                make_uint4(hw[0], hw[1], hw[2], hw[3]);
            *reinterpret_cast<uint4*>(&AHI[wbase + 4]) =
                make_uint4(hw[4], hw[5], hw[6], hw[7]);
            *reinterpret_cast<uint4*>(&ALO[wbase]) =
                make_uint4(lw[0], lw[1], lw[2], lw[3]);
            *reinterpret_cast<uint4*>(&ALO[wbase + 4]) =
                make_uint4(lw[4], lw[5], lw[6], lw[7]);
        }
        __syncthreads();

        float acc[4][2][4];
#pragma unroll
        for (int nt = 0; nt < 4; nt++)
#pragma unroll
            for (int f = 0; f < 2; f++)
#pragma unroll
                for (int e = 0; e < 4; e++) acc[nt][f][e] = 0.f;

#pragma unroll
        for (int s = 0; s < 8; s++) {
            unsigned ah[2][4], al[2][4];
#pragma unroll
            for (int f = 0; f < 2; f++) {
                ldsm_x4(ah[f], ahi_b + (unsigned)(aoff[f] + s * 8) * 4u);
                ldsm_x4(al[f], alo_b + (unsigned)(aoff[f] + s * 8) * 4u);
            }
#pragma unroll
            for (int nt = 0; nt < 4; nt++) {
                if (nt < ncnt) {
                    const int bw = (((s * 25 + ntb + nt) * 32) + lane) * 2;
                    const unsigned long long bh =
                        *reinterpret_cast<const unsigned long long*>(&BHI[bw]);
                    const unsigned long long bl =
                        *reinterpret_cast<const unsigned long long*>(&BLO[bw]);
                    const unsigned bh0 = (unsigned)bh, bh1 = (unsigned)(bh >> 32);
                    const unsigned bl0 = (unsigned)bl, bl1 = (unsigned)(bl >> 32);
#pragma unroll
                    for (int f = 0; f < 2; f++) {
                        mma_bf16(acc[nt][f], ah[f], bh0, bh1);
                        mma_bf16(acc[nt][f], ah[f], bl0, bl1);
                        mma_bf16(acc[nt][f], al[f], bh0, bh1);
                    }
                }
            }
        }

#pragma unroll
        for (int nt = 0; nt < 4; nt++) {
            if (nt < ncnt) {
                const int col = (ntb + nt) * 8 + 2 * c_ln;
                const float bx = bsum[col];
                const float by = bsum[col + 1];
#pragma unroll
                for (int f = 0; f < 2; f++) {
                    const int row = row0 + wm * 32 + f * 16 + r_ln;
                    float2 o0, o1;
                    o0.x = acc[nt][f][0] + bx;
                    o0.y = acc[nt][f][1] + by;
                    o1.x = acc[nt][f][2] + bx;
                    o1.y = acc[nt][f][3] + by;
                    *reinterpret_cast<float2*>(
                        &g_xproj[(size_t)row * 200 + col]) = o0;
                    *reinterpret_cast<float2*>(
                        &g_xproj[(size_t)(row + 8) * 200 + col]) = o1;
                }
            }
        }
        __syncthreads();
    }
}

// ---------------------------------------------------------------------------
// K2: LSTM recurrence. R14 skeleton (rotated roles, dedicated loader warps)
// + R15 change: gate threads apply their OWN activation in phase 1
// (v in [100,150) -> tanh via 2*sigm(2d)-1, else sigmoid) and store the
// ACTIVATED value. Phase 2 shrinks to: read 4 acts, cell fma, tanh(c), store.
// ---------------------------------------------------------------------------
#define S_ 8

__global__ __launch_bounds__(512, 1) void k2_lstm(const float* __restrict__ Whh)
{
    __shared__ __align__(16) float h_s[2][52];
    __shared__ float gates_s[2][200];
    __shared__ __align__(16) float xs[2][S_][200];

    const int tid = threadIdx.x;
    const int g   = tid >> 8;
    const int n   = tid & 255;
    const int v   = g ? ((n + 64) & 255) : n;   // rotated role index
    const int b   = blockIdx.x * 2 + g;

    const bool gate   = (v < 200);
    const bool isg    = (v >= 100 && v < 150);  // tanh gate
    const bool loader = (v >= 200 && v < 250);
    const int  lj     = v - 200;

    unsigned long long w2[25];
    if (gate) {
        const float2* wr = reinterpret_cast<const float2*>(Whh + v * 50);
#pragma unroll
        for (int q = 0; q < 25; q++)
            w2[q] = *reinterpret_cast<const unsigned long long*>(&wr[q]);
    }
    if (v < 52) h_s[g][v] = 0.f;

    if (loader) {
#pragma unroll
        for (int s = 0; s < S_ - 1; s++) {
            cp16(smem_u32(&xs[g][s][lj * 4]),
                 g_xproj + ((size_t)(s * B_ + b) * 200) + lj * 4);
            asm volatile("cp.async.commit_group;");
        }
        asm volatile("cp.async.wait_group %0;" :: "n"(S_ - 3));
    }
    __syncthreads();

    float c = 0.f;

    for (int t = 0; t < T_; t++) {
        const int slot = t & (S_ - 1);

        if (loader) {
            const int ts = t + S_ - 1;
            if (ts < T_)
                cp16(smem_u32(&xs[g][ts & (S_ - 1)][lj * 4]),
                     g_xproj + ((size_t)(ts * B_ + b) * 200) + lj * 4);
            asm volatile("cp.async.commit_group;");
        }

        // ---- phase 1: gate dot + own activation ----
        if (gate) {
            const float xp = xs[g][slot][v];
            const unsigned long long* h2 =
                reinterpret_cast<const unsigned long long*>(h_s[g]);
            unsigned long long a0 = 0ull, a1 = 0ull, a2 = 0ull, a3 = 0ull;
#pragma unroll
            for (int q = 0; q < 24; q += 4) {
                a0 = fma2(h2[q],     w2[q],     a0);
                a1 = fma2(h2[q + 1], w2[q + 1], a1);
                a2 = fma2(h2[q + 2], w2[q + 2], a2);
                a3 = fma2(h2[q + 3], w2[q + 3], a3);
            }
            a0 = fma2(h2[24], w2[24], a0);
            a0 = add2(a0, a1);
            a2 = add2(a2, a3);
            a0 = add2(a0, a2);
            const float2 s = u2f(a0);
            const float d = xp + s.x + s.y;
            gates_s[g][v] = isg ? fmaf(2.f, sigm(2.f * d), -1.f) : sigm(d);
        } else if (loader) {
            asm volatile("cp.async.wait_group %0;" :: "n"(S_ - 3));
        }
        asm volatile("bar.sync %0, 256;" :: "r"(g + 1) : "memory");

        // ---- phase 2: cell update (activations pre-applied) ----
        if (v < 50) {
            const float si = gates_s[g][v];
            const float sf = gates_s[g][v + 50];
            const float tg = gates_s[g][v + 100];
            const float so = gates_s[g][v + 150];
            c = fmaf(sf, c, si * tg);
            const float tc = fmaf(2.f, sigm(2.f * c), -1.f);
            const float hn = so * tc;
            h_s[g][v] = hn;
            g_hs[(size_t)(t * B_ + b) * 50 + v] = hn;
        }
        asm volatile("bar.sync %0, 256;" :: "r"(g + 1) : "memory");
    }
}

// ---------------------------------------------------------------------------
// K3 (v2): head with coalesced smem staging (unchanged from R14)
// ---------------------------------------------------------------------------
#define K3_SMEM_WORDS (12800 + 800 + 144 + 16 + 9)

__global__ __launch_bounds__(256) void k3_head(
    const float* __restrict__ W1, const float* __restrict__ b1,
    const float* __restrict__ W2, const float* __restrict__ b2,
    float* __restrict__ out)
{
    extern __shared__ __align__(16) float k3sm[];
    float* sh  = k3sm;
    float* sW1 = k3sm + 12800;
    float* sW2 = k3sm + 13600;
    float* sb1 = k3sm + 13744;
    float* sb2 = k3sm + 13760;

    const int tid = threadIdx.x;

    {
        const float4* src = reinterpret_cast<const float4*>(
            g_hs + (size_t)blockIdx.x * 12800);
        float4* dst = reinterpret_cast<float4*>(sh);
        for (int i = tid; i < 3200; i += 256) dst[i] = src[i];
    }
    for (int i = tid; i < 800; i += 256) sW1[i] = W1[i];
    if (tid < 144) sW2[tid] = W2[tid];
    if (tid < 16)  sb1[tid] = b1[tid];
    if (tid < 9)   sb2[tid] = b2[tid];
    __syncthreads();

    const int r = blockIdx.x * 256 + tid;
    const float* hrow = &sh[tid * 50];

    float z[16];
#pragma unroll
    for (int jj = 0; jj < 16; jj++) {
        float a = sb1[jj];
#pragma unroll
        for (int k = 0; k < 50; k++) a = fmaf(hrow[k], sW1[jj * 50 + k], a);
        z[jj] = fmaxf(a, 0.f);
    }
#pragma unroll
    for (int pp = 0; pp < 9; pp++) {
        float o = sb2[pp];
#pragma unroll
        for (int jj = 0; jj < 16; jj++) o = fmaf(z[jj], sW2[pp * 16 + jj], o);
        out[r * 9 + pp] = o;
    }
}

// ---------------------------------------------------------------------------
extern "C" void kernel_launch(void* const* d_in, const int* in_sizes, int n_in,
                              void* d_out, int out_size)
{
    const int*   tokens = (const int*)  d_in[0];
    const float* emb    = (const float*)d_in[1];
    const float* Wih    = (const float*)d_in[2];
    const float* Whh    = (const float*)d_in[3];
    const float* bih    = (const float*)d_in[4];
    const float* bhh    = (const float*)d_in[5];
    const float* W1     = (const float*)d_in[6];
    const float* b1     = (const float*)d_in[7];
    const float* W2     = (const float*)d_in[8];
    const float* b2     = (const float*)d_in[9];
    float* out = (float*)d_out;

    const int k1_smem = K1_SMEM_WORDS * 4;   // 138,016 B
    cudaFuncSetAttribute(k1_mma, cudaFuncAttributeMaxDynamicSharedMemorySize,
                         k1_smem);
    const int k3_smem = K3_SMEM_WORDS * 4;   // 55,076 B
    cudaFuncSetAttribute(k3_head, cudaFuncAttributeMaxDynamicSharedMemorySize,
                         k3_smem);

    k1_mma  <<<148, 512, k1_smem>>>(tokens, emb, Wih, bih, bhh);
    k2_lstm <<<B_ / 2, 512>>>(Whh);
    k3_head <<<M_ / 256, 256, k3_smem>>>(W1, b1, W2, b2, out);
}